// round 7
// baseline (speedup 1.0000x reference)
#include <cuda_runtime.h>

#define N_VARS 2048
#define P      8
#define BATCH  4096
#define ROW    (N_VARS * P)      // 16384
#define COLS4  (N_VARS / 4)      // 512
#define THREADS 256
#define GATHER_BLOCKS 64         // 64*256 = 16384 diag elements, one per thread

__device__ float g_diag[P * N_VARS];          // gathered diagonal (64 KB)
__device__ unsigned int g_arrive = 0;         // gather blocks completed
__device__ unsigned int g_passed = 0;         // blocks past the spin (replay reset)

__global__ __launch_bounds__(THREADS) void diag_linear_onekernel(
    const float*  __restrict__ weight,  // (2048, 16384)
    const float4* __restrict__ x,       // (4096, 16384) as float4
    float4*       __restrict__ out)     // (4096, 2048)  as float4
{
    const unsigned int bid = blockIdx.x;
    const int t = threadIdx.x;

    // ---- phase 1: first 64 blocks gather the diagonal ----
    if (bid < GATHER_BLOCKS) {
        int idx = bid * THREADS + t;          // 0 .. 16383
        int lag = idx >> 11;                  // / N_VARS
        int i   = idx & (N_VARS - 1);         // % N_VARS
        g_diag[idx] = __ldg(&weight[(size_t)i * ROW + lag * N_VARS + i]);
        __threadfence();                      // release: publish stores
        __syncthreads();                      // all stores in block done
        if (t == 0) atomicAdd(&g_arrive, 1u);
    }

    // ---- phase 2: PRE-ISSUE all 8 x loads (independent of the gather) ----
    int tid = bid * THREADS + t;              // 0 .. BATCH*COLS4-1
    int b = tid / COLS4;
    int c = tid - b * COLS4;
    const float4* xrow = x + (size_t)b * (ROW / 4);

    float4 xv[P];
    #pragma unroll
    for (int lag = 0; lag < P; lag++)
        xv[lag] = __ldg(&xrow[lag * COLS4 + c]);

    // ---- phase 3: gate — spin hidden under the in-flight x loads ----
    if (t == 0) {
        volatile unsigned int* f = &g_arrive;
        unsigned int ns = 32;
        while (*f < GATHER_BLOCKS) {
            __nanosleep(ns);
            if (ns < 256) ns <<= 1;           // backoff to lighten L2 polling
        }
        __threadfence();                      // acquire
        // replay-safe reset: the LAST block through clears the counters
        unsigned int p = atomicAdd(&g_passed, 1u) + 1u;
        if (p == gridDim.x) {
            g_arrive = 0u;
            g_passed = 0u;
            __threadfence();
        }
    }
    __syncthreads();

    // ---- phase 4: contraction (coherent diag loads — written this launch) ----
    const float4* diag4 = reinterpret_cast<const float4*>(g_diag);
    float4 acc;
    acc.x = 0.f; acc.y = 0.f; acc.z = 0.f; acc.w = 0.f;

    #pragma unroll
    for (int lag = 0; lag < P; lag++) {
        float4 dv = diag4[lag * COLS4 + c];   // L2-hot, 64 KB working set
        acc.x = fmaf(xv[lag].x, dv.x, acc.x);
        acc.y = fmaf(xv[lag].y, dv.y, acc.y);
        acc.z = fmaf(xv[lag].z, dv.z, acc.z);
        acc.w = fmaf(xv[lag].w, dv.w, acc.w);
    }
    out[tid] = acc;
}

extern "C" void kernel_launch(void* const* d_in, const int* in_sizes, int n_in,
                              void* d_out, int out_size) {
    const float* x      = (const float*)d_in[0];   // (4096, 16384)
    const float* weight = (const float*)d_in[1];   // (2048, 16384)
    float* out          = (float*)d_out;           // (4096, 2048)

    const int total = BATCH * COLS4;               // 2,097,152 threads
    diag_linear_onekernel<<<total / THREADS, THREADS>>>(
        weight,
        reinterpret_cast<const float4*>(x),
        reinterpret_cast<float4*>(out));
}

// round 8
// speedup vs baseline: 1.1179x; 1.1179x over previous
#include <cuda_runtime.h>

#define N_VARS 2048
#define P      8
#define BATCH  4096
#define ROW    (N_VARS * P)      // 16384
#define COLS4  (N_VARS / 4)      // 512
#define THREADS 256

// 64 KB scratch: diag[lag*N_VARS + i] = weight[i, lag*N_VARS + i]
__device__ float g_diag[P * N_VARS];

__global__ __launch_bounds__(THREADS) void gather_diag_kernel(
    const float* __restrict__ weight)
{
    int idx = blockIdx.x * THREADS + threadIdx.x;  // 0 .. 16383
    int lag = idx >> 11;                           // / N_VARS
    int i   = idx & (N_VARS - 1);                  // % N_VARS
    g_diag[idx] = __ldg(&weight[(size_t)i * ROW + lag * N_VARS + i]);
}

__global__ __launch_bounds__(THREADS) void diag_linear_kernel(
    const float4* __restrict__ x,    // (4096, 16384) as float4
    float4*       __restrict__ out)  // (4096, 2048)  as float4
{
    int tid = blockIdx.x * THREADS + threadIdx.x;  // 0 .. BATCH*COLS4-1
    int b = tid / COLS4;
    int c = tid - b * COLS4;

    const float4* xrow  = x + (size_t)b * (ROW / 4);
    const float4* diag4 = reinterpret_cast<const float4*>(g_diag);

    float4 acc;
    acc.x = 0.f; acc.y = 0.f; acc.z = 0.f; acc.w = 0.f;

    #pragma unroll
    for (int lag = 0; lag < P; lag++) {
        float4 xv = __ldcs(&xrow[lag * COLS4 + c]);   // stream: read once, evict first
        float4 dv = __ldg(&diag4[lag * COLS4 + c]);   // hot 64 KB, written by prev kernel
        acc.x = fmaf(xv.x, dv.x, acc.x);
        acc.y = fmaf(xv.y, dv.y, acc.y);
        acc.z = fmaf(xv.z, dv.z, acc.z);
        acc.w = fmaf(xv.w, dv.w, acc.w);
    }
    __stcs(&out[tid], acc);                           // stream store: no reuse
}

extern "C" void kernel_launch(void* const* d_in, const int* in_sizes, int n_in,
                              void* d_out, int out_size) {
    const float* x      = (const float*)d_in[0];   // (4096, 16384)
    const float* weight = (const float*)d_in[1];   // (2048, 16384)
    float* out          = (float*)d_out;           // (4096, 2048)

    // 1) gather diagonal (16384 threads, one scattered load each)
    gather_diag_kernel<<<(P * N_VARS) / THREADS, THREADS>>>(weight);

    // 2) streaming diagonal contraction (proven 32-reg / high-occupancy body)
    diag_linear_kernel<<<(BATCH * COLS4) / THREADS, THREADS>>>(
        reinterpret_cast<const float4*>(x),
        reinterpret_cast<float4*>(out));
}